// round 1
// baseline (speedup 1.0000x reference)
#include <cuda_runtime.h>
#include <math.h>

#define Bc 2
#define Nc 2048
#define Dc 1024
#define Hc 16
#define DHc 64
#define E3 192   // 3*DH, chunk order in last dim is k(0:64), q(64:128), v(128:192)

// Scratch (allocation-free rule: __device__ globals)
__device__ float g_kqv[Bc * Hc * Nc * E3];   // [b,h,n,192]
__device__ float g_sa[Bc * Nc * Dc];         // [b,n,d] concat-head attention output

// ---------------------------------------------------------------------------
// GEMM1: kqv[b,h,n,e] = x[b,n,:] @ W_kqv[h,:,e] + b_kqv[h,e]
// A = x viewed as [4096, 1024]; logical B[k, col] with col = h*192+e.
// 64-wide column tiles never cross a head boundary (64 | 192).
// ---------------------------------------------------------------------------
__global__ __launch_bounds__(256) void gemm_kqv_kernel(
    const float* __restrict__ x, const float* __restrict__ Wk,
    const float* __restrict__ bk)
{
    __shared__ float As[16][64];
    __shared__ float Bs[16][64];
    const int tid = threadIdx.x;
    const int tx = tid & 15, ty = tid >> 4;
    const int c0 = blockIdx.x * 64;        // column tile (h*192+e space, 3072 wide)
    const int r0 = blockIdx.y * 64;        // row tile (b*N+n space, 4096 tall)
    const int hblk = c0 / E3;
    const int e0 = c0 - hblk * E3;
    const float* Bp = Wk + (size_t)hblk * Dc * E3 + e0;

    const int am  = tid >> 2;              // 0..63  (row within A tile)
    const int ak4 = (tid & 3) * 4;         // 0..12  (k within A tile, float4)
    const int bkk = tid >> 4;              // 0..15  (k within B tile)
    const int bc4 = (tid & 15) * 4;        // 0..60  (col within B tile, float4)

    float acc[4][4] = {};
    for (int k0 = 0; k0 < Dc; k0 += 16) {
        float4 av = *(const float4*)&x[(size_t)(r0 + am) * Dc + k0 + ak4];
        As[ak4 + 0][am] = av.x; As[ak4 + 1][am] = av.y;
        As[ak4 + 2][am] = av.z; As[ak4 + 3][am] = av.w;
        *(float4*)&Bs[bkk][bc4] =
            *(const float4*)&Bp[(size_t)(k0 + bkk) * E3 + bc4];
        __syncthreads();
        #pragma unroll
        for (int kk = 0; kk < 16; kk++) {
            float4 a = *(const float4*)&As[kk][ty * 4];
            float4 b = *(const float4*)&Bs[kk][tx * 4];
            float aa[4] = {a.x, a.y, a.z, a.w};
            float bb[4] = {b.x, b.y, b.z, b.w};
            #pragma unroll
            for (int i = 0; i < 4; i++)
                #pragma unroll
                for (int j = 0; j < 4; j++)
                    acc[i][j] += aa[i] * bb[j];
        }
        __syncthreads();
    }
    #pragma unroll
    for (int i = 0; i < 4; i++) {
        int gr = r0 + ty * 4 + i;          // b*N + n
        int b = gr >> 11;                  // / 2048
        int n = gr & 2047;
        #pragma unroll
        for (int j = 0; j < 4; j++) {
            int gc = c0 + tx * 4 + j;      // h*192 + e
            int e = gc - hblk * E3;
            g_kqv[(((size_t)(b * Hc + hblk)) * Nc + n) * E3 + e] =
                acc[i][j] + bk[gc];
        }
    }
}

// ---------------------------------------------------------------------------
// Attention: per (b,h), flash-style online softmax.
// Block = 128 threads, one query row per thread (q + acc live in registers).
// K/V tiles of 64 keys in SMEM; all lanes read the same SMEM word -> broadcast.
// ---------------------------------------------------------------------------
__global__ __launch_bounds__(128) void attn_kernel()
{
    __shared__ float Ks[64][64];
    __shared__ float Vs[64][64];
    const int t = threadIdx.x;
    const int bh = blockIdx.y;             // b*H + h
    const int b = bh >> 4, h = bh & 15;
    const int r0 = blockIdx.x * 128;
    const int r = r0 + t;

    const float* base = g_kqv + (size_t)bh * Nc * E3;

    // load q row (scaled by 1/sqrt(DH) = 0.125)
    float q[64];
    {
        const float* qp = base + (size_t)r * E3 + 64;
        #pragma unroll
        for (int d = 0; d < 64; d += 4) {
            float4 v = *(const float4*)&qp[d];
            q[d] = v.x * 0.125f; q[d + 1] = v.y * 0.125f;
            q[d + 2] = v.z * 0.125f; q[d + 3] = v.w * 0.125f;
        }
    }

    float acc[64] = {};
    float m = -1e30f, l = 0.f;

    const int ntiles = r0 / 64 + 2;        // last tile needed by row r0+127
    for (int kt = 0; kt < ntiles; kt++) {
        const float* kb = base + (size_t)(kt * 64) * E3;       // k chunk
        const float* vb = kb + 128;                            // v chunk
        #pragma unroll
        for (int i = 0; i < 8; i++) {      // 128 thr * 8 * float4 = 4096 floats
            int lin = i * 512 + t * 4;
            int kk = lin >> 6, d = lin & 63;
            *(float4*)&Ks[kk][d] = *(const float4*)&kb[(size_t)kk * E3 + d];
            *(float4*)&Vs[kk][d] = *(const float4*)&vb[(size_t)kk * E3 + d];
        }
        __syncthreads();

        int kmax = r - kt * 64 + 1;        // causal bound within this tile
        if (kmax > 64) kmax = 64;
        for (int kk = 0; kk < kmax; kk++) {
            float s0 = 0.f, s1 = 0.f, s2 = 0.f, s3 = 0.f;
            #pragma unroll
            for (int d = 0; d < 64; d += 4) {
                s0 += q[d + 0] * Ks[kk][d + 0];
                s1 += q[d + 1] * Ks[kk][d + 1];
                s2 += q[d + 2] * Ks[kk][d + 2];
                s3 += q[d + 3] * Ks[kk][d + 3];
            }
            float s = (s0 + s1) + (s2 + s3);
            float mn = fmaxf(m, s);
            float corr = __expf(m - mn);
            float p = __expf(s - mn);
            l = l * corr + p;
            m = mn;
            #pragma unroll
            for (int d = 0; d < 64; d++)
                acc[d] = acc[d] * corr + p * Vs[kk][d];
        }
        __syncthreads();
    }

    const float inv = 1.f / l;
    float* op = g_sa + ((size_t)(b * Nc + r)) * Dc + h * 64;
    #pragma unroll
    for (int d = 0; d < 64; d += 4) {
        float4 v;
        v.x = acc[d] * inv; v.y = acc[d + 1] * inv;
        v.z = acc[d + 2] * inv; v.w = acc[d + 3] * inv;
        *(float4*)&op[d] = v;
    }
}

// ---------------------------------------------------------------------------
// GEMM2: out[r, j] = sum_d sa[r, d] * W_proj[j, d] + b_proj[j]   (A @ B^T)
// ---------------------------------------------------------------------------
__global__ __launch_bounds__(256) void gemm_proj_kernel(
    const float* __restrict__ Wp, const float* __restrict__ bp,
    float* __restrict__ out)
{
    __shared__ float As[16][64];
    __shared__ float Bs[16][64];
    const int tid = threadIdx.x;
    const int tx = tid & 15, ty = tid >> 4;
    const int c0 = blockIdx.x * 64;
    const int r0 = blockIdx.y * 64;

    const int am  = tid >> 2;              // 0..63
    const int ak4 = (tid & 3) * 4;         // 0..12
    const int bc  = tid >> 2;              // 0..63 (output col)
    const int bk4 = (tid & 3) * 4;         // 0..12

    float acc[4][4] = {};
    for (int k0 = 0; k0 < Dc; k0 += 16) {
        float4 av = *(const float4*)&g_sa[(size_t)(r0 + am) * Dc + k0 + ak4];
        As[ak4 + 0][am] = av.x; As[ak4 + 1][am] = av.y;
        As[ak4 + 2][am] = av.z; As[ak4 + 3][am] = av.w;
        // B^T[k, col] = Wp[col*D + k] : load 4 consecutive k, store transposed
        float4 bv = *(const float4*)&Wp[(size_t)(c0 + bc) * Dc + k0 + bk4];
        Bs[bk4 + 0][bc] = bv.x; Bs[bk4 + 1][bc] = bv.y;
        Bs[bk4 + 2][bc] = bv.z; Bs[bk4 + 3][bc] = bv.w;
        __syncthreads();
        #pragma unroll
        for (int kk = 0; kk < 16; kk++) {
            float4 a = *(const float4*)&As[kk][ty * 4];
            float4 b = *(const float4*)&Bs[kk][tx * 4];
            float aa[4] = {a.x, a.y, a.z, a.w};
            float bb[4] = {b.x, b.y, b.z, b.w};
            #pragma unroll
            for (int i = 0; i < 4; i++)
                #pragma unroll
                for (int j = 0; j < 4; j++)
                    acc[i][j] += aa[i] * bb[j];
        }
        __syncthreads();
    }
    #pragma unroll
    for (int i = 0; i < 4; i++) {
        int gr = r0 + ty * 4 + i;
        #pragma unroll
        for (int j = 0; j < 4; j++) {
            int gc = c0 + tx * 4 + j;
            out[(size_t)gr * Dc + gc] = acc[i][j] + bp[gc];
        }
    }
}

extern "C" void kernel_launch(void* const* d_in, const int* in_sizes, int n_in,
                              void* d_out, int out_size)
{
    const float* x  = (const float*)d_in[0];
    const float* Wk = (const float*)d_in[1];
    const float* bk = (const float*)d_in[2];
    const float* Wp = (const float*)d_in[3];
    const float* bp = (const float*)d_in[4];
    float* out = (float*)d_out;

    dim3 g1(48, 64);   // 3072/64 cols, 4096/64 rows
    gemm_kqv_kernel<<<g1, 256>>>(x, Wk, bk);

    dim3 g2(16, 32);   // 2048/128 row-tiles, B*H
    attn_kernel<<<g2, 128>>>();

    dim3 g3(16, 64);   // 1024/64 cols, 4096/64 rows
    gemm_proj_kernel<<<g3, 256>>>(Wp, bp, out);
}

// round 2
// speedup vs baseline: 1.5157x; 1.5157x over previous
#include <cuda_runtime.h>
#include <math.h>

#define Bc 2
#define Nc 2048
#define Dc 1024
#define Hc 16
#define DHc 64
#define E3 192   // 3*DH; chunk order k(0:64), q(64:128), v(128:192)

__device__ float g_kqv[Bc * Hc * Nc * E3];   // [b,h,n,192]
__device__ float g_sa[Bc * Nc * Dc];         // [b,n,d]

// ---------------------------------------------------------------------------
// GEMM1: kqv = x @ W_kqv + b_kqv. Tile 256x64, 256 threads, 8x8 microtile.
// 64-wide col tiles never cross a head boundary (64 | 192).
// ---------------------------------------------------------------------------
__global__ __launch_bounds__(256) void gemm_kqv_kernel(
    const float* __restrict__ x, const float* __restrict__ Wk,
    const float* __restrict__ bk)
{
    __shared__ float As[16][256];   // [k][row]
    __shared__ float Bs[16][64];    // [k][col]
    const int t = threadIdx.x;
    const int c0 = blockIdx.x * 64;
    const int r0 = blockIdx.y * 256;
    const int hblk = c0 / E3;
    const int e0 = c0 - hblk * E3;
    const float* Bp = Wk + (size_t)hblk * Dc * E3 + e0;
    const int row_t = (t & 3) | ((t >> 5) << 2);   // 0..31
    const int col_t = (t >> 2) & 7;                // 0..7

    float4 a_pref[4], b_pref;
    #pragma unroll
    for (int it = 0; it < 4; it++)
        a_pref[it] = *(const float4*)&x[(size_t)(r0 + t) * Dc + it * 4];
    b_pref = *(const float4*)&Bp[(size_t)(t >> 4) * E3 + (t & 15) * 4];

    float acc[8][8] = {};
    for (int k0 = 0; k0 < Dc; k0 += 16) {
        #pragma unroll
        for (int it = 0; it < 4; it++) {
            As[it*4+0][t] = a_pref[it].x; As[it*4+1][t] = a_pref[it].y;
            As[it*4+2][t] = a_pref[it].z; As[it*4+3][t] = a_pref[it].w;
        }
        *(float4*)&Bs[t >> 4][(t & 15) * 4] = b_pref;
        __syncthreads();
        if (k0 + 16 < Dc) {
            #pragma unroll
            for (int it = 0; it < 4; it++)
                a_pref[it] = *(const float4*)&x[(size_t)(r0 + t) * Dc + k0 + 16 + it * 4];
            b_pref = *(const float4*)&Bp[(size_t)(k0 + 16 + (t >> 4)) * E3 + (t & 15) * 4];
        }
        #pragma unroll
        for (int kk = 0; kk < 16; kk++) {
            float4 a0 = *(const float4*)&As[kk][row_t * 4];
            float4 a1 = *(const float4*)&As[kk][128 + row_t * 4];
            float4 b0 = *(const float4*)&Bs[kk][col_t * 4];
            float4 b1 = *(const float4*)&Bs[kk][32 + col_t * 4];
            float aa[8] = {a0.x,a0.y,a0.z,a0.w,a1.x,a1.y,a1.z,a1.w};
            float bb[8] = {b0.x,b0.y,b0.z,b0.w,b1.x,b1.y,b1.z,b1.w};
            #pragma unroll
            for (int i = 0; i < 8; i++)
                #pragma unroll
                for (int j = 0; j < 8; j++)
                    acc[i][j] += aa[i] * bb[j];
        }
        __syncthreads();
    }

    float4 bias0 = *(const float4*)&bk[hblk * E3 + e0 + col_t * 4];
    float4 bias1 = *(const float4*)&bk[hblk * E3 + e0 + 32 + col_t * 4];
    float bb0[4] = {bias0.x, bias0.y, bias0.z, bias0.w};
    float bb1[4] = {bias1.x, bias1.y, bias1.z, bias1.w};
    #pragma unroll
    for (int i = 0; i < 8; i++) {
        int gr = r0 + ((i < 4) ? (row_t * 4 + i) : (128 + row_t * 4 + i - 4));
        int b = gr >> 11;
        int n = gr & 2047;
        float* op = g_kqv + (((size_t)(b * Hc + hblk)) * Nc + n) * E3 + e0;
        float4 o0, o1;
        o0.x = acc[i][0] + bb0[0]; o0.y = acc[i][1] + bb0[1];
        o0.z = acc[i][2] + bb0[2]; o0.w = acc[i][3] + bb0[3];
        o1.x = acc[i][4] + bb1[0]; o1.y = acc[i][5] + bb1[1];
        o1.z = acc[i][6] + bb1[2]; o1.w = acc[i][7] + bb1[3];
        *(float4*)&op[col_t * 4] = o0;
        *(float4*)&op[32 + col_t * 4] = o1;
    }
}

// ---------------------------------------------------------------------------
// Attention: flash-style, 64x64 score tile per 128-thread block.
// Microtile: 4 rows x 8 cols per thread. P reuses K's smem buffer.
// ---------------------------------------------------------------------------
__global__ __launch_bounds__(128) void attn_kernel()
{
    __shared__ float Qs[64][64];    // [d][r]  (q, pre-scaled)
    __shared__ float KPs[64][64];   // K as [d][c]; then P as [c][r]
    __shared__ float Vs[64][64];    // [c][d]
    const int t = threadIdx.x;
    const int bh = blockIdx.y;
    const int b = bh >> 4, h = bh & 15;
    const int qt = (int)gridDim.x - 1 - (int)blockIdx.x;  // heavy blocks first
    const int q0 = qt * 64;
    const int row_t = (t & 3) | ((t >> 5) << 2);   // 0..15
    const int col_t = (t >> 2) & 7;                // 0..7
    const float* base = g_kqv + (size_t)bh * Nc * E3;

    // Q load: transposed, scaled by 1/sqrt(64)
    #pragma unroll
    for (int it = 0; it < 8; it++) {
        int task = it * 128 + t;
        int r = task & 63, d4 = (task >> 6) * 4;
        float4 v = *(const float4*)&base[(size_t)(q0 + r) * E3 + 64 + d4];
        Qs[d4 + 0][r] = v.x * 0.125f; Qs[d4 + 1][r] = v.y * 0.125f;
        Qs[d4 + 2][r] = v.z * 0.125f; Qs[d4 + 3][r] = v.w * 0.125f;
    }

    float m[4], l[4], O[4][8];
    #pragma unroll
    for (int i = 0; i < 4; i++) {
        m[i] = -1e30f; l[i] = 0.f;
        #pragma unroll
        for (int j = 0; j < 8; j++) O[i][j] = 0.f;
    }

    for (int kt = 0; kt <= qt; kt++) {
        const int k0 = kt * 64;
        __syncthreads();   // protect KPs/Vs (prev iter) and Q (first iter)
        #pragma unroll
        for (int it = 0; it < 8; it++) {       // K transposed
            int task = it * 128 + t;
            int c = task & 63, d4 = (task >> 6) * 4;
            float4 v = *(const float4*)&base[(size_t)(k0 + c) * E3 + d4];
            KPs[d4 + 0][c] = v.x; KPs[d4 + 1][c] = v.y;
            KPs[d4 + 2][c] = v.z; KPs[d4 + 3][c] = v.w;
        }
        #pragma unroll
        for (int it = 0; it < 8; it++) {       // V natural
            int task = it * 128 + t;
            int c = task >> 4, d4 = (task & 15) * 4;
            *(float4*)&Vs[c][d4] =
                *(const float4*)&base[(size_t)(k0 + c) * E3 + 128 + d4];
        }
        __syncthreads();

        // S = Q K^T
        float S[4][8] = {};
        #pragma unroll
        for (int d = 0; d < 64; d++) {
            float4 qv  = *(const float4*)&Qs[d][row_t * 4];
            float4 k0v = *(const float4*)&KPs[d][col_t * 4];
            float4 k1v = *(const float4*)&KPs[d][32 + col_t * 4];
            float qq[4] = {qv.x, qv.y, qv.z, qv.w};
            float kk_[8] = {k0v.x,k0v.y,k0v.z,k0v.w,k1v.x,k1v.y,k1v.z,k1v.w};
            #pragma unroll
            for (int i = 0; i < 4; i++)
                #pragma unroll
                for (int j = 0; j < 8; j++)
                    S[i][j] += qq[i] * kk_[j];
        }

        if (kt == qt) {   // causal mask on diagonal tile
            #pragma unroll
            for (int i = 0; i < 4; i++) {
                int rr = row_t * 4 + i;
                #pragma unroll
                for (int j = 0; j < 8; j++) {
                    int cc = (j < 4) ? (col_t * 4 + j) : (32 + col_t * 4 + j - 4);
                    if (cc > rr) S[i][j] = -1e30f;
                }
            }
        }

        // online softmax update
        #pragma unroll
        for (int i = 0; i < 4; i++) {
            float tm = S[i][0];
            #pragma unroll
            for (int j = 1; j < 8; j++) tm = fmaxf(tm, S[i][j]);
            tm = fmaxf(tm, __shfl_xor_sync(0xffffffffu, tm, 4));
            tm = fmaxf(tm, __shfl_xor_sync(0xffffffffu, tm, 8));
            tm = fmaxf(tm, __shfl_xor_sync(0xffffffffu, tm, 16));
            float mn = fmaxf(m[i], tm);
            float corr = __expf(m[i] - mn);
            float sum = 0.f;
            #pragma unroll
            for (int j = 0; j < 8; j++) {
                S[i][j] = __expf(S[i][j] - mn);
                sum += S[i][j];
            }
            sum += __shfl_xor_sync(0xffffffffu, sum, 4);
            sum += __shfl_xor_sync(0xffffffffu, sum, 8);
            sum += __shfl_xor_sync(0xffffffffu, sum, 16);
            l[i] = l[i] * corr + sum;
            m[i] = mn;
            #pragma unroll
            for (int j = 0; j < 8; j++) O[i][j] *= corr;
        }
        __syncthreads();   // done reading K from KPs

        // write P transposed: KPs[c][r]
        #pragma unroll
        for (int j = 0; j < 8; j++) {
            int c = (j < 4) ? (col_t * 4 + j) : (32 + col_t * 4 + j - 4);
            float4 pv;
            pv.x = S[0][j]; pv.y = S[1][j]; pv.z = S[2][j]; pv.w = S[3][j];
            *(float4*)&KPs[c][row_t * 4] = pv;
        }
        __syncthreads();

        // O += P V
        #pragma unroll 8
        for (int kk = 0; kk < 64; kk++) {
            float4 pv = *(const float4*)&KPs[kk][row_t * 4];
            float4 v0 = *(const float4*)&Vs[kk][col_t * 4];
            float4 v1 = *(const float4*)&Vs[kk][32 + col_t * 4];
            float pp[4] = {pv.x, pv.y, pv.z, pv.w};
            float vv[8] = {v0.x,v0.y,v0.z,v0.w,v1.x,v1.y,v1.z,v1.w};
            #pragma unroll
            for (int i = 0; i < 4; i++)
                #pragma unroll
                for (int j = 0; j < 8; j++)
                    O[i][j] += pp[i] * vv[j];
        }
    }

    #pragma unroll
    for (int i = 0; i < 4; i++) {
        float inv = 1.f / l[i];
        int r = q0 + row_t * 4 + i;
        float* op = g_sa + ((size_t)(b * Nc + r)) * Dc + h * 64;
        float4 o0, o1;
        o0.x = O[i][0]*inv; o0.y = O[i][1]*inv; o0.z = O[i][2]*inv; o0.w = O[i][3]*inv;
        o1.x = O[i][4]*inv; o1.y = O[i][5]*inv; o1.z = O[i][6]*inv; o1.w = O[i][7]*inv;
        *(float4*)&op[col_t * 4] = o0;
        *(float4*)&op[32 + col_t * 4] = o1;
    }
}

// ---------------------------------------------------------------------------
// GEMM2: out = sa @ W_proj^T + b_proj. Tile 128x128, 256 threads, 8x8 micro.
// ---------------------------------------------------------------------------
__global__ __launch_bounds__(256) void gemm_proj_kernel(
    const float* __restrict__ Wp, const float* __restrict__ bp,
    float* __restrict__ out)
{
    __shared__ float As[16][128];   // [k][row]
    __shared__ float Bs[16][128];   // [k][col]  (B = Wp^T)
    const int t = threadIdx.x;
    const int c0 = blockIdx.x * 128;
    const int r0 = blockIdx.y * 128;
    const int row_t = t >> 4;   // 0..15
    const int col_t = t & 15;   // 0..15

    float4 a_pref[2], b_pref[2];
    #pragma unroll
    for (int it = 0; it < 2; it++) {
        int task = it * 256 + t;
        int rr = task & 127, kg = task >> 7;
        a_pref[it] = *(const float4*)&g_sa[(size_t)(r0 + rr) * Dc + kg * 4];
        b_pref[it] = *(const float4*)&Wp[(size_t)(c0 + rr) * Dc + kg * 4];
    }

    float acc[8][8] = {};
    for (int k0 = 0; k0 < Dc; k0 += 16) {
        #pragma unroll
        for (int it = 0; it < 2; it++) {
            int task = it * 256 + t;
            int rr = task & 127, kg = task >> 7;
            As[kg*4+0][rr] = a_pref[it].x; As[kg*4+1][rr] = a_pref[it].y;
            As[kg*4+2][rr] = a_pref[it].z; As[kg*4+3][rr] = a_pref[it].w;
            Bs[kg*4+0][rr] = b_pref[it].x; Bs[kg*4+1][rr] = b_pref[it].y;
            Bs[kg*4+2][rr] = b_pref[it].z; Bs[kg*4+3][rr] = b_pref[it].w;
        }
        __syncthreads();
        if (k0 + 16 < Dc) {
            #pragma unroll
            for (int it = 0; it < 2; it++) {
                int task = it * 256 + t;
                int rr = task & 127, kg = task >> 7;
                a_pref[it] = *(const float4*)&g_sa[(size_t)(r0 + rr) * Dc + k0 + 16 + kg * 4];
                b_pref[it] = *(const float4*)&Wp[(size_t)(c0 + rr) * Dc + k0 + 16 + kg * 4];
            }
        }
        #pragma unroll
        for (int kk = 0; kk < 16; kk++) {
            float4 a0 = *(const float4*)&As[kk][row_t * 4];
            float4 a1 = *(const float4*)&As[kk][64 + row_t * 4];
            float4 b0 = *(const float4*)&Bs[kk][col_t * 4];
            float4 b1 = *(const float4*)&Bs[kk][64 + col_t * 4];
            float aa[8] = {a0.x,a0.y,a0.z,a0.w,a1.x,a1.y,a1.z,a1.w};
            float bb[8] = {b0.x,b0.y,b0.z,b0.w,b1.x,b1.y,b1.z,b1.w};
            #pragma unroll
            for (int i = 0; i < 8; i++)
                #pragma unroll
                for (int j = 0; j < 8; j++)
                    acc[i][j] += aa[i] * bb[j];
        }
        __syncthreads();
    }

    float4 bias0 = *(const float4*)&bp[c0 + col_t * 4];
    float4 bias1 = *(const float4*)&bp[c0 + 64 + col_t * 4];
    float bb0[4] = {bias0.x, bias0.y, bias0.z, bias0.w};
    float bb1[4] = {bias1.x, bias1.y, bias1.z, bias1.w};
    #pragma unroll
    for (int i = 0; i < 8; i++) {
        int gr = r0 + ((i < 4) ? (row_t * 4 + i) : (64 + row_t * 4 + i - 4));
        float4 o0, o1;
        o0.x = acc[i][0] + bb0[0]; o0.y = acc[i][1] + bb0[1];
        o0.z = acc[i][2] + bb0[2]; o0.w = acc[i][3] + bb0[3];
        o1.x = acc[i][4] + bb1[0]; o1.y = acc[i][5] + bb1[1];
        o1.z = acc[i][6] + bb1[2]; o1.w = acc[i][7] + bb1[3];
        *(float4*)&out[(size_t)gr * Dc + c0 + col_t * 4] = o0;
        *(float4*)&out[(size_t)gr * Dc + c0 + 64 + col_t * 4] = o1;
    }
}

extern "C" void kernel_launch(void* const* d_in, const int* in_sizes, int n_in,
                              void* d_out, int out_size)
{
    const float* x  = (const float*)d_in[0];
    const float* Wk = (const float*)d_in[1];
    const float* bk = (const float*)d_in[2];
    const float* Wp = (const float*)d_in[3];
    const float* bp = (const float*)d_in[4];
    float* out = (float*)d_out;

    dim3 g1(48, 16);   // 3072/64 cols, 4096/256 rows
    gemm_kqv_kernel<<<g1, 256>>>(x, Wk, bk);

    dim3 g2(32, 32);   // 2048/64 q-tiles, B*H
    attn_kernel<<<g2, 128>>>();

    dim3 g3(8, 32);    // 1024/128 cols, 4096/128 rows
    gemm_proj_kernel<<<g3, 256>>>(Wp, bp, out);
}

// round 5
// speedup vs baseline: 2.7007x; 1.7818x over previous
#include <cuda_runtime.h>
#include <cstdint>
#include <math.h>

#define Bc 2
#define Nc 2048
#define Dc 1024
#define Hc 16
#define E3 192   // 3*DH; chunk order k(0:64), q(64:128), v(128:192)

__device__ float g_kqv[Bc * Hc * Nc * E3];   // [b,h,n,192]
__device__ float g_sa[Bc * Nc * Dc];         // [b,n,d]
__device__ float g_WkT[Hc * E3 * Dc];        // W_kqv as [c=h*192+e][k] (K-major)

__device__ __forceinline__ float to_tf32(float v) {
    float r;
    asm("cvt.rna.tf32.f32 %0, %1;" : "=f"(r) : "f"(v));
    return r;
}
__device__ __forceinline__ float4 to_tf32_4(float4 v) {
    float4 r;
    r.x = to_tf32(v.x); r.y = to_tf32(v.y); r.z = to_tf32(v.z); r.w = to_tf32(v.w);
    return r;
}
__device__ __forceinline__ void mma_tf32(float* c, const uint32_t* a, const uint32_t* b) {
    asm volatile(
        "mma.sync.aligned.m16n8k8.row.col.f32.tf32.tf32.f32 "
        "{%0,%1,%2,%3}, {%4,%5,%6,%7}, {%8,%9}, {%0,%1,%2,%3};"
        : "+f"(c[0]), "+f"(c[1]), "+f"(c[2]), "+f"(c[3])
        : "r"(a[0]), "r"(a[1]), "r"(a[2]), "r"(a[3]), "r"(b[0]), "r"(b[1]));
}

// ---------------------------------------------------------------------------
// Transpose W_kqv [H][D][E3] -> g_WkT [H*E3][D]
// ---------------------------------------------------------------------------
__global__ __launch_bounds__(256) void transpose_wk(const float* __restrict__ Wk)
{
    __shared__ float tile[32][33];
    const int e0 = blockIdx.x * 32, k0 = blockIdx.y * 32, h = blockIdx.z;
    const float* src = Wk + (size_t)h * Dc * E3;
    float* dst = g_WkT + (size_t)h * E3 * Dc;
    const int tx = threadIdx.x & 31, ty0 = threadIdx.x >> 5;
    #pragma unroll
    for (int i = 0; i < 4; i++) {
        int ty = ty0 + i * 8;
        tile[ty][tx] = src[(size_t)(k0 + ty) * E3 + e0 + tx];
    }
    __syncthreads();
    #pragma unroll
    for (int i = 0; i < 4; i++) {
        int ty = ty0 + i * 8;
        dst[(size_t)(e0 + ty) * Dc + k0 + tx] = tile[tx][ty];
    }
}

// ---------------------------------------------------------------------------
// tf32 mma.sync GEMM: out[128 x 128] per CTA.
// KQV=true : A = x (param), B = g_WkT (device global), out -> g_kqv
// KQV=false: A = g_sa (device global), B = W_proj (param), out row-major
// 256 threads = 8 warps (2 M x 4 N); warp tile 64x32 = 4x4 m16n8k8.
// K slab 32 (4 k8 steps), single smem buffer + register prefetch.
// NOTE: __device__ globals must be referenced from DEVICE code only.
// ---------------------------------------------------------------------------
#define SMP 36   // padded k-stride (words)
template<bool KQV>
__global__ __launch_bounds__(256) void gemm_mma(
    const float* __restrict__ Aparam, const float* __restrict__ Bparam,
    const float* __restrict__ bias, float* __restrict__ outp)
{
    const float* __restrict__ A    = KQV ? Aparam : (const float*)g_sa;
    const float* __restrict__ Bmat = KQV ? (const float*)g_WkT : Bparam;

    __shared__ float As[128 * SMP];
    __shared__ float Bs[128 * SMP];
    const int t = threadIdx.x;
    const int lane = t & 31;
    const int warp = t >> 5;
    const int mbase = (warp >> 2) * 64;
    const int nbase = (warp & 3) * 32;
    const int grp = lane >> 2;       // 0..7
    const int ctg = lane & 3;        // 0..3
    const int c0 = blockIdx.x * 128;
    const int r0 = blockIdx.y * 128;

    const int ld_row = t >> 3;       // 0..31
    const int ld_kq  = (t & 7) * 4;  // 0..28

    float4 pa[4], pb[4];
    #pragma unroll
    for (int it = 0; it < 4; it++) {
        int row = it * 32 + ld_row;
        pa[it] = *(const float4*)&A[(size_t)(r0 + row) * Dc + ld_kq];
        pb[it] = *(const float4*)&Bmat[(size_t)(c0 + row) * Dc + ld_kq];
    }

    float C[4][4][4];
    #pragma unroll
    for (int i = 0; i < 4; i++)
        #pragma unroll
        for (int j = 0; j < 4; j++)
            #pragma unroll
            for (int k = 0; k < 4; k++) C[i][j][k] = 0.f;

    for (int s = 0; s < 32; s++) {
        #pragma unroll
        for (int it = 0; it < 4; it++) {
            int row = it * 32 + ld_row;
            *(float4*)&As[row * SMP + ld_kq] = to_tf32_4(pa[it]);
            *(float4*)&Bs[row * SMP + ld_kq] = to_tf32_4(pb[it]);
        }
        __syncthreads();
        if (s < 31) {
            const int k0n = (s + 1) * 32;
            #pragma unroll
            for (int it = 0; it < 4; it++) {
                int row = it * 32 + ld_row;
                pa[it] = *(const float4*)&A[(size_t)(r0 + row) * Dc + k0n + ld_kq];
                pb[it] = *(const float4*)&Bmat[(size_t)(c0 + row) * Dc + k0n + ld_kq];
            }
        }
        #pragma unroll
        for (int kk = 0; kk < 4; kk++) {
            uint32_t af[4][4], bf[4][2];
            const int kof = kk * 8 + ctg;
            #pragma unroll
            for (int tm = 0; tm < 4; tm++) {
                const int m = mbase + tm * 16 + grp;
                af[tm][0] = __float_as_uint(As[m * SMP + kof]);
                af[tm][1] = __float_as_uint(As[(m + 8) * SMP + kof]);
                af[tm][2] = __float_as_uint(As[m * SMP + kof + 4]);
                af[tm][3] = __float_as_uint(As[(m + 8) * SMP + kof + 4]);
            }
            #pragma unroll
            for (int tn = 0; tn < 4; tn++) {
                const int n = nbase + tn * 8 + grp;
                bf[tn][0] = __float_as_uint(Bs[n * SMP + kof]);
                bf[tn][1] = __float_as_uint(Bs[n * SMP + kof + 4]);
            }
            #pragma unroll
            for (int tm = 0; tm < 4; tm++)
                #pragma unroll
                for (int tn = 0; tn < 4; tn++)
                    mma_tf32(C[tm][tn], af[tm], bf[tn]);
        }
        __syncthreads();
    }

    // Epilogue: C thread layout — rows grp/grp+8, cols 2*ctg, 2*ctg+1
    #pragma unroll
    for (int tm = 0; tm < 4; tm++) {
        #pragma unroll
        for (int tn = 0; tn < 4; tn++) {
            const int c = c0 + nbase + tn * 8 + ctg * 2;
            const float bs0 = bias[c], bs1 = bias[c + 1];
            #pragma unroll
            for (int half = 0; half < 2; half++) {
                const int row = r0 + mbase + tm * 16 + grp + half * 8;
                float2 o;
                o.x = C[tm][tn][half * 2 + 0] + bs0;
                o.y = C[tm][tn][half * 2 + 1] + bs1;
                if (KQV) {
                    const int h = c / E3;
                    const int e = c - h * E3;
                    const int b = row >> 11, n = row & 2047;
                    *(float2*)&g_kqv[(((size_t)(b * Hc + h)) * Nc + n) * E3 + e] = o;
                } else {
                    *(float2*)&outp[(size_t)row * Dc + c] = o;
                }
            }
        }
    }
}

// ---------------------------------------------------------------------------
// Attention: flash-style, 64x64 score tile per 128-thread block (unchanged).
// ---------------------------------------------------------------------------
__global__ __launch_bounds__(128) void attn_kernel()
{
    __shared__ float Qs[64][64];
    __shared__ float KPs[64][64];
    __shared__ float Vs[64][64];
    const int t = threadIdx.x;
    const int bh = blockIdx.y;
    const int b = bh >> 4, h = bh & 15;
    const int qt = (int)gridDim.x - 1 - (int)blockIdx.x;
    const int q0 = qt * 64;
    const int row_t = (t & 3) | ((t >> 5) << 2);
    const int col_t = (t >> 2) & 7;
    const float* base = g_kqv + (size_t)bh * Nc * E3;

    #pragma unroll
    for (int it = 0; it < 8; it++) {
        int task = it * 128 + t;
        int r = task & 63, d4 = (task >> 6) * 4;
        float4 v = *(const float4*)&base[(size_t)(q0 + r) * E3 + 64 + d4];
        Qs[d4 + 0][r] = v.x * 0.125f; Qs[d4 + 1][r] = v.y * 0.125f;
        Qs[d4 + 2][r] = v.z * 0.125f; Qs[d4 + 3][r] = v.w * 0.125f;
    }

    float m[4], l[4], O[4][8];
    #pragma unroll
    for (int i = 0; i < 4; i++) {
        m[i] = -1e30f; l[i] = 0.f;
        #pragma unroll
        for (int j = 0; j < 8; j++) O[i][j] = 0.f;
    }

    for (int kt = 0; kt <= qt; kt++) {
        const int k0 = kt * 64;
        __syncthreads();
        #pragma unroll
        for (int it = 0; it < 8; it++) {
            int task = it * 128 + t;
            int c = task & 63, d4 = (task >> 6) * 4;
            float4 v = *(const float4*)&base[(size_t)(k0 + c) * E3 + d4];
            KPs[d4 + 0][c] = v.x; KPs[d4 + 1][c] = v.y;
            KPs[d4 + 2][c] = v.z; KPs[d4 + 3][c] = v.w;
        }
        #pragma unroll
        for (int it = 0; it < 8; it++) {
            int task = it * 128 + t;
            int c = task >> 4, d4 = (task & 15) * 4;
            *(float4*)&Vs[c][d4] =
                *(const float4*)&base[(size_t)(k0 + c) * E3 + 128 + d4];
        }
        __syncthreads();

        float S[4][8] = {};
        #pragma unroll
        for (int d = 0; d < 64; d++) {
            float4 qv  = *(const float4*)&Qs[d][row_t * 4];
            float4 k0v = *(const float4*)&KPs[d][col_t * 4];
            float4 k1v = *(const float4*)&KPs[d][32 + col_t * 4];
            float qq[4] = {qv.x, qv.y, qv.z, qv.w};
            float kk_[8] = {k0v.x,k0v.y,k0v.z,k0v.w,k1v.x,k1v.y,k1v.z,k1v.w};
            #pragma unroll
            for (int i = 0; i < 4; i++)
                #pragma unroll
                for (int j = 0; j < 8; j++)
                    S[i][j] += qq[i] * kk_[j];
        }

        if (kt == qt) {
            #pragma unroll
            for (int i = 0; i < 4; i++) {
                int rr = row_t * 4 + i;
                #pragma unroll
                for (int j = 0; j < 8; j++) {
                    int cc = (j < 4) ? (col_t * 4 + j) : (32 + col_t * 4 + j - 4);
                    if (cc > rr) S[i][j] = -1e30f;
                }
            }
        }

        #pragma unroll
        for (int i = 0; i < 4; i++) {
            float tm = S[i][0];
            #pragma unroll
            for (int j = 1; j < 8; j++) tm = fmaxf(tm, S[i][j]);
            tm = fmaxf(tm, __shfl_xor_sync(0xffffffffu, tm, 4));
            tm = fmaxf(tm, __shfl_xor_sync(0xffffffffu, tm, 8));
            tm = fmaxf(tm, __shfl_xor_sync(0xffffffffu, tm, 16));
            float mn = fmaxf(m[i], tm);
            float corr = __expf(m[i] - mn);
            float sum = 0.f;
            #pragma unroll
            for (int j = 0; j < 8; j++) {
                S[i][j] = __expf(S[i][j] - mn);
                sum += S[i][j];
            }
            sum += __shfl_xor_sync(0xffffffffu, sum, 4);
            sum += __shfl_xor_sync(0xffffffffu, sum, 8);
            sum += __shfl_xor_sync(0xffffffffu, sum, 16);
            l[i] = l[i] * corr + sum;
            m[i] = mn;
            #pragma unroll
            for (int j = 0; j < 8; j++) O[i][j] *= corr;
        }
        __syncthreads();

        #pragma unroll
        for (int j = 0; j < 8; j++) {
            int c = (j < 4) ? (col_t * 4 + j) : (32 + col_t * 4 + j - 4);
            float4 pv;
            pv.x = S[0][j]; pv.y = S[1][j]; pv.z = S[2][j]; pv.w = S[3][j];
            *(float4*)&KPs[c][row_t * 4] = pv;
        }
        __syncthreads();

        #pragma unroll 8
        for (int kk = 0; kk < 64; kk++) {
            float4 pv = *(const float4*)&KPs[kk][row_t * 4];
            float4 v0 = *(const float4*)&Vs[kk][col_t * 4];
            float4 v1 = *(const float4*)&Vs[kk][32 + col_t * 4];
            float pp[4] = {pv.x, pv.y, pv.z, pv.w};
            float vv[8] = {v0.x,v0.y,v0.z,v0.w,v1.x,v1.y,v1.z,v1.w};
            #pragma unroll
            for (int i = 0; i < 4; i++)
                #pragma unroll
                for (int j = 0; j < 8; j++)
                    O[i][j] += pp[i] * vv[j];
        }
    }

    #pragma unroll
    for (int i = 0; i < 4; i++) {
        float inv = 1.f / l[i];
        int r = q0 + row_t * 4 + i;
        float* op = g_sa + ((size_t)(b * Nc + r)) * Dc + h * 64;
        float4 o0, o1;
        o0.x = O[i][0]*inv; o0.y = O[i][1]*inv; o0.z = O[i][2]*inv; o0.w = O[i][3]*inv;
        o1.x = O[i][4]*inv; o1.y = O[i][5]*inv; o1.z = O[i][6]*inv; o1.w = O[i][7]*inv;
        *(float4*)&op[col_t * 4] = o0;
        *(float4*)&op[32 + col_t * 4] = o1;
    }
}

extern "C" void kernel_launch(void* const* d_in, const int* in_sizes, int n_in,
                              void* d_out, int out_size)
{
    const float* x  = (const float*)d_in[0];
    const float* Wk = (const float*)d_in[1];
    const float* bk = (const float*)d_in[2];
    const float* Wp = (const float*)d_in[3];
    const float* bp = (const float*)d_in[4];
    float* out = (float*)d_out;

    transpose_wk<<<dim3(6, 32, 16), 256>>>(Wk);

    gemm_mma<true><<<dim3(24, 32), 256>>>(x, nullptr, bk, nullptr);

    attn_kernel<<<dim3(32, 32), 128>>>();

    gemm_mma<false><<<dim3(8, 32), 256>>>(nullptr, Wp, bp, out);
}

// round 7
// speedup vs baseline: 4.7464x; 1.7575x over previous
#include <cuda_runtime.h>
#include <cstdint>
#include <math.h>

#define Bc 2
#define Nc 2048
#define Dc 1024
#define Hc 16
#define E3 192   // 3*DH; chunk order k(0:64), q(64:128), v(128:192)

__device__ float g_kqv[Bc * Hc * Nc * E3];   // [b,h,n,192]
__device__ float g_sa[Bc * Nc * Dc];         // [b,n,d]
__device__ float g_WkT[Hc * E3 * Dc];        // W_kqv as [c=h*192+e][k] (K-major)

__device__ __forceinline__ float to_tf32(float v) {
    float r;
    asm("cvt.rna.tf32.f32 %0, %1;" : "=f"(r) : "f"(v));
    return r;
}
__device__ __forceinline__ float4 to_tf32_4(float4 v) {
    float4 r;
    r.x = to_tf32(v.x); r.y = to_tf32(v.y); r.z = to_tf32(v.z); r.w = to_tf32(v.w);
    return r;
}
__device__ __forceinline__ void mma_tf32(float* c, const uint32_t* a, const uint32_t* b) {
    asm volatile(
        "mma.sync.aligned.m16n8k8.row.col.f32.tf32.tf32.f32 "
        "{%0,%1,%2,%3}, {%4,%5,%6,%7}, {%8,%9}, {%0,%1,%2,%3};"
        : "+f"(c[0]), "+f"(c[1]), "+f"(c[2]), "+f"(c[3])
        : "r"(a[0]), "r"(a[1]), "r"(a[2]), "r"(a[3]), "r"(b[0]), "r"(b[1]));
}

// ---------------------------------------------------------------------------
// Transpose W_kqv [H][D][E3] -> g_WkT [H*E3][D]
// ---------------------------------------------------------------------------
__global__ __launch_bounds__(256) void transpose_wk(const float* __restrict__ Wk)
{
    __shared__ float tile[32][33];
    const int e0 = blockIdx.x * 32, k0 = blockIdx.y * 32, h = blockIdx.z;
    const float* src = Wk + (size_t)h * Dc * E3;
    float* dst = g_WkT + (size_t)h * E3 * Dc;
    const int tx = threadIdx.x & 31, ty0 = threadIdx.x >> 5;
    #pragma unroll
    for (int i = 0; i < 4; i++) {
        int ty = ty0 + i * 8;
        tile[ty][tx] = src[(size_t)(k0 + ty) * E3 + e0 + tx];
    }
    __syncthreads();
    #pragma unroll
    for (int i = 0; i < 4; i++) {
        int ty = ty0 + i * 8;
        dst[(size_t)(e0 + ty) * Dc + k0 + tx] = tile[tx][ty];
    }
}

// ---------------------------------------------------------------------------
// tf32 mma.sync GEMM: out[128 x 128] per CTA (unchanged from round 5).
// ---------------------------------------------------------------------------
#define SMP 36
template<bool KQV>
__global__ __launch_bounds__(256) void gemm_mma(
    const float* __restrict__ Aparam, const float* __restrict__ Bparam,
    const float* __restrict__ bias, float* __restrict__ outp)
{
    const float* __restrict__ A    = KQV ? Aparam : (const float*)g_sa;
    const float* __restrict__ Bmat = KQV ? (const float*)g_WkT : Bparam;

    __shared__ float As[128 * SMP];
    __shared__ float Bs[128 * SMP];
    const int t = threadIdx.x;
    const int lane = t & 31;
    const int warp = t >> 5;
    const int mbase = (warp >> 2) * 64;
    const int nbase = (warp & 3) * 32;
    const int grp = lane >> 2;
    const int ctg = lane & 3;
    const int c0 = blockIdx.x * 128;
    const int r0 = blockIdx.y * 128;

    const int ld_row = t >> 3;
    const int ld_kq  = (t & 7) * 4;

    float4 pa[4], pb[4];
    #pragma unroll
    for (int it = 0; it < 4; it++) {
        int row = it * 32 + ld_row;
        pa[it] = *(const float4*)&A[(size_t)(r0 + row) * Dc + ld_kq];
        pb[it] = *(const float4*)&Bmat[(size_t)(c0 + row) * Dc + ld_kq];
    }

    float C[4][4][4];
    #pragma unroll
    for (int i = 0; i < 4; i++)
        #pragma unroll
        for (int j = 0; j < 4; j++)
            #pragma unroll
            for (int k = 0; k < 4; k++) C[i][j][k] = 0.f;

    for (int s = 0; s < 32; s++) {
        #pragma unroll
        for (int it = 0; it < 4; it++) {
            int row = it * 32 + ld_row;
            *(float4*)&As[row * SMP + ld_kq] = to_tf32_4(pa[it]);
            *(float4*)&Bs[row * SMP + ld_kq] = to_tf32_4(pb[it]);
        }
        __syncthreads();
        if (s < 31) {
            const int k0n = (s + 1) * 32;
            #pragma unroll
            for (int it = 0; it < 4; it++) {
                int row = it * 32 + ld_row;
                pa[it] = *(const float4*)&A[(size_t)(r0 + row) * Dc + k0n + ld_kq];
                pb[it] = *(const float4*)&Bmat[(size_t)(c0 + row) * Dc + k0n + ld_kq];
            }
        }
        #pragma unroll
        for (int kk = 0; kk < 4; kk++) {
            uint32_t af[4][4], bf[4][2];
            const int kof = kk * 8 + ctg;
            #pragma unroll
            for (int tm = 0; tm < 4; tm++) {
                const int m = mbase + tm * 16 + grp;
                af[tm][0] = __float_as_uint(As[m * SMP + kof]);
                af[tm][1] = __float_as_uint(As[(m + 8) * SMP + kof]);
                af[tm][2] = __float_as_uint(As[m * SMP + kof + 4]);
                af[tm][3] = __float_as_uint(As[(m + 8) * SMP + kof + 4]);
            }
            #pragma unroll
            for (int tn = 0; tn < 4; tn++) {
                const int n = nbase + tn * 8 + grp;
                bf[tn][0] = __float_as_uint(Bs[n * SMP + kof]);
                bf[tn][1] = __float_as_uint(Bs[n * SMP + kof + 4]);
            }
            #pragma unroll
            for (int tm = 0; tm < 4; tm++)
                #pragma unroll
                for (int tn = 0; tn < 4; tn++)
                    mma_tf32(C[tm][tn], af[tm], bf[tn]);
        }
        __syncthreads();
    }

    #pragma unroll
    for (int tm = 0; tm < 4; tm++) {
        #pragma unroll
        for (int tn = 0; tn < 4; tn++) {
            const int c = c0 + nbase + tn * 8 + ctg * 2;
            const float bs0 = bias[c], bs1 = bias[c + 1];
            #pragma unroll
            for (int half = 0; half < 2; half++) {
                const int row = r0 + mbase + tm * 16 + grp + half * 8;
                float2 o;
                o.x = C[tm][tn][half * 2 + 0] + bs0;
                o.y = C[tm][tn][half * 2 + 1] + bs1;
                if (KQV) {
                    const int h = c / E3;
                    const int e = c - h * E3;
                    const int b = row >> 11, n = row & 2047;
                    *(float2*)&g_kqv[(((size_t)(b * Hc + h)) * Nc + n) * E3 + e] = o;
                } else {
                    *(float2*)&outp[(size_t)row * Dc + c] = o;
                }
            }
        }
    }
}

// ---------------------------------------------------------------------------
// Attention on tensor cores: flash-style, 64x64 tile, 4 warps x 16 q-rows.
// QK^T and P*V via m16n8k8 tf32 mma. Q fragments + O accumulators in regs.
// Smem (dynamic 53248B): Ks[64][68], QPs[64][68] (Q then P), Vs[64][72].
// All fragment LDS patterns bank-conflict-free by stride choice (68, 68, 72).
// ---------------------------------------------------------------------------
#define ATTN_SMEM 53248
__global__ __launch_bounds__(128) void attn_mma()
{
    extern __shared__ float sm[];
    float* Ks  = sm;           // stride 68
    float* QPs = sm + 4352;    // stride 68 (Q staged, then P per-warp bands)
    float* Vs  = sm + 8704;    // stride 72

    const int t = threadIdx.x;
    const int lane = t & 31, warp = t >> 5;
    const int grp = lane >> 2, ctg = lane & 3;
    const int mb = warp * 16;
    const int bh = blockIdx.y;
    const int b = bh >> 4, h = bh & 15;
    const int qt = (int)gridDim.x - 1 - (int)blockIdx.x;   // heavy blocks first
    const int q0 = qt * 64;
    const float* base = g_kqv + (size_t)bh * Nc * E3;

    // ---- stage Q (scaled by 1/8, tf32), extract A-fragments to registers ----
    #pragma unroll
    for (int it = 0; it < 8; it++) {
        int task = it * 128 + t;
        int c = task >> 4, d4 = (task & 15) * 4;
        float4 v = *(const float4*)&base[(size_t)(q0 + c) * E3 + 64 + d4];
        v.x = to_tf32(v.x * 0.125f); v.y = to_tf32(v.y * 0.125f);
        v.z = to_tf32(v.z * 0.125f); v.w = to_tf32(v.w * 0.125f);
        *(float4*)&QPs[c * 68 + d4] = v;
    }
    __syncthreads();
    uint32_t qf[8][4];
    #pragma unroll
    for (int kk = 0; kk < 8; kk++) {
        qf[kk][0] = __float_as_uint(QPs[(mb + grp) * 68 + kk * 8 + ctg]);
        qf[kk][1] = __float_as_uint(QPs[(mb + grp + 8) * 68 + kk * 8 + ctg]);
        qf[kk][2] = __float_as_uint(QPs[(mb + grp) * 68 + kk * 8 + ctg + 4]);
        qf[kk][3] = __float_as_uint(QPs[(mb + grp + 8) * 68 + kk * 8 + ctg + 4]);
    }

    float OC[8][4];
    #pragma unroll
    for (int i = 0; i < 8; i++)
        #pragma unroll
        for (int j = 0; j < 4; j++) OC[i][j] = 0.f;
    float m0 = -1e30f, m1 = -1e30f, l0 = 0.f, l1 = 0.f;

    for (int kt = 0; kt <= qt; kt++) {
        const int k0 = kt * 64;
        __syncthreads();   // prev iter done reading Ks/Vs
        #pragma unroll
        for (int it = 0; it < 8; it++) {   // K tile [key][dim]
            int task = it * 128 + t;
            int c = task >> 4, d4 = (task & 15) * 4;
            float4 v = to_tf32_4(*(const float4*)&base[(size_t)(k0 + c) * E3 + d4]);
            *(float4*)&Ks[c * 68 + d4] = v;
        }
        #pragma unroll
        for (int it = 0; it < 8; it++) {   // V tile [key][dim]
            int task = it * 128 + t;
            int c = task >> 4, d4 = (task & 15) * 4;
            float4 v = to_tf32_4(*(const float4*)&base[(size_t)(k0 + c) * E3 + 128 + d4]);
            *(float4*)&Vs[c * 72 + d4] = v;
        }
        __syncthreads();

        // ---- S = Q K^T : B-frag b0 = K[nt*8+grp][kk*8+ctg] ----
        float SC[8][4];
        #pragma unroll
        for (int i = 0; i < 8; i++)
            #pragma unroll
            for (int j = 0; j < 4; j++) SC[i][j] = 0.f;
        #pragma unroll
        for (int kk = 0; kk < 8; kk++) {
            #pragma unroll
            for (int nt = 0; nt < 8; nt++) {
                uint32_t bf[2];
                bf[0] = __float_as_uint(Ks[(nt * 8 + grp) * 68 + kk * 8 + ctg]);
                bf[1] = __float_as_uint(Ks[(nt * 8 + grp) * 68 + kk * 8 + ctg + 4]);
                mma_tf32(SC[nt], qf[kk], bf);
            }
        }

        // ---- causal mask on diagonal tile ----
        if (kt == qt) {
            const int r0l = mb + grp, r1l = mb + grp + 8;
            #pragma unroll
            for (int nt = 0; nt < 8; nt++) {
                const int col = nt * 8 + 2 * ctg;
                if (col > r0l)     SC[nt][0] = -1e30f;
                if (col + 1 > r0l) SC[nt][1] = -1e30f;
                if (col > r1l)     SC[nt][2] = -1e30f;
                if (col + 1 > r1l) SC[nt][3] = -1e30f;
            }
        }

        // ---- online softmax on fragments (rows grp, grp+8) ----
        float tm0 = -1e30f, tm1 = -1e30f;
        #pragma unroll
        for (int nt = 0; nt < 8; nt++) {
            tm0 = fmaxf(tm0, fmaxf(SC[nt][0], SC[nt][1]));
            tm1 = fmaxf(tm1, fmaxf(SC[nt][2], SC[nt][3]));
        }
        tm0 = fmaxf(tm0, __shfl_xor_sync(0xffffffffu, tm0, 1));
        tm0 = fmaxf(tm0, __shfl_xor_sync(0xffffffffu, tm0, 2));
        tm1 = fmaxf(tm1, __shfl_xor_sync(0xffffffffu, tm1, 1));
        tm1 = fmaxf(tm1, __shfl_xor_sync(0xffffffffu, tm1, 2));
        const float mn0 = fmaxf(m0, tm0), mn1 = fmaxf(m1, tm1);
        const float corr0 = __expf(m0 - mn0), corr1 = __expf(m1 - mn1);
        m0 = mn0; m1 = mn1;
        float s0 = 0.f, s1 = 0.f;
        #pragma unroll
        for (int nt = 0; nt < 8; nt++) {
            SC[nt][0] = __expf(SC[nt][0] - mn0); s0 += SC[nt][0];
            SC[nt][1] = __expf(SC[nt][1] - mn0); s0 += SC[nt][1];
            SC[nt][2] = __expf(SC[nt][2] - mn1); s1 += SC[nt][2];
            SC[nt][3] = __expf(SC[nt][3] - mn1); s1 += SC[nt][3];
        }
        s0 += __shfl_xor_sync(0xffffffffu, s0, 1);
        s0 += __shfl_xor_sync(0xffffffffu, s0, 2);
        s1 += __shfl_xor_sync(0xffffffffu, s1, 1);
        s1 += __shfl_xor_sync(0xffffffffu, s1, 2);
        l0 = l0 * corr0 + s0;
        l1 = l1 * corr1 + s1;
        #pragma unroll
        for (int nt = 0; nt < 8; nt++) {
            OC[nt][0] *= corr0; OC[nt][1] *= corr0;
            OC[nt][2] *= corr1; OC[nt][3] *= corr1;
        }

        // ---- store P into warp-private band of QPs (tf32) ----
        #pragma unroll
        for (int nt = 0; nt < 8; nt++) {
            float2 p0, p1;
            p0.x = to_tf32(SC[nt][0]); p0.y = to_tf32(SC[nt][1]);
            p1.x = to_tf32(SC[nt][2]); p1.y = to_tf32(SC[nt][3]);
            *(float2*)&QPs[(mb + grp) * 68 + nt * 8 + 2 * ctg] = p0;
            *(float2*)&QPs[(mb + grp + 8) * 68 + nt * 8 + 2 * ctg] = p1;
        }
        __syncwarp();

        // ---- O += P V : A-frag from QPs band, B-frag b0 = V[kk*8+ctg][dt*8+grp] ----
        #pragma unroll
        for (int kk = 0; kk < 8; kk++) {
            uint32_t af[4];
            af[0] = __float_as_uint(QPs[(mb + grp) * 68 + kk * 8 + ctg]);
            af[1] = __float_as_uint(QPs[(mb + grp + 8) * 68 + kk * 8 + ctg]);
            af[2] = __float_as_uint(QPs[(mb + grp) * 68 + kk * 8 + ctg + 4]);
            af[3] = __float_as_uint(QPs[(mb + grp + 8) * 68 + kk * 8 + ctg + 4]);
            #pragma unroll
            for (int dt = 0; dt < 8; dt++) {
                uint32_t bf[2];
                bf[0] = __float_as_uint(Vs[(kk * 8 + ctg) * 72 + dt * 8 + grp]);
                bf[1] = __float_as_uint(Vs[(kk * 8 + ctg + 4) * 72 + dt * 8 + grp]);
                mma_tf32(OC[dt], af, bf);
            }
        }
    }

    // ---- epilogue: O / l -> g_sa ----
    const float inv0 = 1.f / l0, inv1 = 1.f / l1;
    const int r0g = b * Nc + q0 + mb + grp;
    #pragma unroll
    for (int dt = 0; dt < 8; dt++) {
        const int c = h * 64 + dt * 8 + 2 * ctg;
        float2 o0, o1;
        o0.x = OC[dt][0] * inv0; o0.y = OC[dt][1] * inv0;
        o1.x = OC[dt][2] * inv1; o1.y = OC[dt][3] * inv1;
        *(float2*)&g_sa[(size_t)r0g * Dc + c] = o0;
        *(float2*)&g_sa[(size_t)(r0g + 8) * Dc + c] = o1;
    }
}

extern "C" void kernel_launch(void* const* d_in, const int* in_sizes, int n_in,
                              void* d_out, int out_size)
{
    const float* x  = (const float*)d_in[0];
    const float* Wk = (const float*)d_in[1];
    const float* bk = (const float*)d_in[2];
    const float* Wp = (const float*)d_in[3];
    const float* bp = (const float*)d_in[4];
    float* out = (float*)d_out;

    cudaFuncSetAttribute((const void*)attn_mma,
                         cudaFuncAttributeMaxDynamicSharedMemorySize, ATTN_SMEM);

    transpose_wk<<<dim3(6, 32, 16), 256>>>(Wk);

    gemm_mma<true><<<dim3(24, 32), 256>>>(x, nullptr, bk, nullptr);

    attn_mma<<<dim3(32, 32), 128, ATTN_SMEM>>>();

    gemm_mma<false><<<dim3(8, 32), 256>>>(nullptr, Wp, bp, out);
}